// round 14
// baseline (speedup 1.0000x reference)
#include <cuda_runtime.h>
#include <cuda_fp16.h>
#include <math.h>
#include <stdint.h>

#define TTOK 2048
#define HDIM 1024
#define ENUM 8
#define IDIM 4096
#define VDIM 32000
#define KTOP 2
#define KC   32

// ---- static scratch (no allocation allowed) ----
__device__ __half g_xh[(size_t)TTOK * HDIM];              // fp16 activations
__device__ __half g_hh[(size_t)ENUM * TTOK * IDIM];       // fp16 expert hidden
__device__ float  g_eo[(size_t)TTOK * HDIM];              // fp32 atomic combine
__device__ __half g_eoh[(size_t)TTOK * HDIM];             // fp16 copy for LM head
__device__ __half g_w1h[(size_t)ENUM * HDIM * IDIM];      // fp16 w1
__device__ __half g_w2h[(size_t)ENUM * IDIM * HDIM];      // fp16 w2
__device__ __half g_lwh[(size_t)HDIM * VDIM];             // fp16 lm_w
__device__ int    g_sel[TTOK * KTOP];
__device__ int    g_list[ENUM][TTOK];
__device__ int    g_cnt[ENUM];

// ======================= helpers =======================
__device__ __forceinline__ uint32_t smem_u32(const void* p) {
    uint32_t a;
    asm("{ .reg .u64 t; cvta.to.shared.u64 t, %1; cvt.u32.u64 %0, t; }" : "=r"(a) : "l"(p));
    return a;
}
// pack two fp32 -> fp16x2 (lo = second operand)
__device__ __forceinline__ uint32_t f2h2(float hi, float lo) {
    uint32_t r;
    asm("cvt.rn.f16x2.f32 %0, %1, %2;" : "=r"(r) : "f"(hi), "f"(lo));
    return r;
}
#define CP16Z(dst, src, sz) \
    asm volatile("cp.async.cg.shared.global [%0], [%1], 16, %2;" \
                 :: "r"(dst), "l"(src), "r"(sz))
#define CPCOMMIT() asm volatile("cp.async.commit_group;")
#define CPWAIT(n)  asm volatile("cp.async.wait_group %0;" :: "n"(n))

#define LDMX4(r, addr)                                                         \
    asm volatile("ldmatrix.sync.aligned.m8n8.x4.shared.b16 {%0,%1,%2,%3}, [%4];" \
        : "=r"((r)[0]), "=r"((r)[1]), "=r"((r)[2]), "=r"((r)[3]) : "r"(addr))

#define LDMX4T(r0, r1, r2, r3, addr)                                           \
    asm volatile("ldmatrix.sync.aligned.m8n8.x4.trans.shared.b16 {%0,%1,%2,%3}, [%4];" \
        : "=r"(r0), "=r"(r1), "=r"(r2), "=r"(r3) : "r"(addr))

#define MMA_F16(d, a, b)                                                       \
    asm volatile(                                                              \
        "mma.sync.aligned.m16n8k16.row.col.f32.f16.f16.f32 "                   \
        "{%0,%1,%2,%3},{%4,%5,%6,%7},{%8,%9},{%0,%1,%2,%3};"                   \
        : "+f"((d)[0]), "+f"((d)[1]), "+f"((d)[2]), "+f"((d)[3])               \
        : "r"((a)[0]), "r"((a)[1]), "r"((a)[2]), "r"((a)[3]),                  \
          "r"((b)[0]), "r"((b)[1]))

// ======================= small kernels =======================
__global__ void cvt_w_kernel(const float* __restrict__ src, __half* __restrict__ dst,
                             int n4) {
    int i = blockIdx.x * blockDim.x + threadIdx.x;
    int stride = gridDim.x * blockDim.x;
    for (; i < n4; i += stride) {
        float4 v = ((const float4*)src)[i];
        uint2 h;
        h.x = f2h2(v.y, v.x);
        h.y = f2h2(v.w, v.z);
        ((uint2*)dst)[i] = h;
    }
}

__global__ void setup_kernel(const int* __restrict__ ids,
                             const float* __restrict__ emb,
                             const float* __restrict__ rw,
                             const float* __restrict__ rb,
                             float* __restrict__ out_rw,
                             float* __restrict__ out_se) {
    int t = blockIdx.x;
    int tid = threadIdx.x;
    int row = ids[t];
    const float* src = emb + (size_t)row * HDIM;
    const float4* s4 = (const float4*)src;
    uint2* dh = (uint2*)(g_xh + (size_t)t * HDIM);
    for (int i = tid; i < HDIM / 4; i += blockDim.x) {
        float4 v = s4[i];
        uint2 h;
        h.x = f2h2(v.y, v.x);
        h.y = f2h2(v.w, v.z);
        dh[i] = h;
    }

    float acc[ENUM];
#pragma unroll
    for (int e = 0; e < ENUM; e++) acc[e] = 0.f;
    for (int k = tid; k < HDIM; k += blockDim.x) {
        float xv = src[k];
        const float* wr = rw + (size_t)k * ENUM;
#pragma unroll
        for (int e = 0; e < ENUM; e++) acc[e] = fmaf(xv, wr[e], acc[e]);
    }
    __shared__ float sred[ENUM][128];
#pragma unroll
    for (int e = 0; e < ENUM; e++) sred[e][tid] = acc[e];
    __syncthreads();
    for (int s = 64; s > 0; s >>= 1) {
        if (tid < s) {
#pragma unroll
            for (int e = 0; e < ENUM; e++) sred[e][tid] += sred[e][tid + s];
        }
        __syncthreads();
    }
    if (tid == 0) {
        float lg[ENUM];
#pragma unroll
        for (int e = 0; e < ENUM; e++) lg[e] = sred[e][0] + rb[e];
        int i0 = 0; float v0 = lg[0];
#pragma unroll
        for (int e = 1; e < ENUM; e++) if (lg[e] > v0) { v0 = lg[e]; i0 = e; }
        int i1 = -1; float v1 = -3.0e38f;
#pragma unroll
        for (int e = 0; e < ENUM; e++) if (e != i0 && lg[e] > v1) { v1 = lg[e]; i1 = e; }
        float ee = expf(v1 - v0);
        float denom = 1.0f + ee;
        g_sel[t * 2 + 0] = i0;
        g_sel[t * 2 + 1] = i1;
        if (out_rw) { out_rw[t * 2 + 0] = 1.0f / denom; out_rw[t * 2 + 1] = ee / denom; }
        if (out_se) { out_se[t * 2 + 0] = (float)i0; out_se[t * 2 + 1] = (float)i1; }
    }
}

__global__ void build_lists_kernel() {
    int e = blockIdx.x;
    int tid = threadIdx.x;
    int lane = tid & 31, wid = tid >> 5;
    __shared__ int wtot[8];
    __shared__ int s_base;
    if (tid == 0) s_base = 0;
    __syncthreads();
    for (int base = 0; base < TTOK; base += 256) {
        int t = base + tid;
        int f = (g_sel[t * 2] == e || g_sel[t * 2 + 1] == e) ? 1 : 0;
        unsigned bal = __ballot_sync(0xffffffffu, f);
        int lpfx = __popc(bal & ((1u << lane) - 1u));
        if (lane == 0) wtot[wid] = __popc(bal);
        __syncthreads();
        int woff = 0;
        for (int w = 0; w < wid; w++) woff += wtot[w];
        if (f) g_list[e][s_base + woff + lpfx] = t;
        int tot = 0;
        for (int w = 0; w < 8; w++) tot += wtot[w];
        __syncthreads();
        if (tid == 0) s_base += tot;
        __syncthreads();
    }
    if (tid == 0) g_cnt[e] = s_base;
}

__global__ void zero_eo_kernel() {
    size_t i = (size_t)blockIdx.x * blockDim.x + threadIdx.x;
    if (i < (size_t)TTOK * HDIM / 4) {
        ((float4*)g_eo)[i] = make_float4(0.f, 0.f, 0.f, 0.f);
    }
}

__global__ void cvt_eo_kernel() {
    size_t i = (size_t)blockIdx.x * blockDim.x + threadIdx.x;
    if (i < (size_t)TTOK * HDIM / 4) {
        float4 v = ((float4*)g_eo)[i];
        uint2 h;
        h.x = f2h2(v.y, v.x);
        h.y = f2h2(v.w, v.z);
        ((uint2*)g_eoh)[i] = h;
    }
}

// ======================= fp16 mma.sync GEMM, fp16 B + ldmatrix.trans =======================
// MODE 0: FFN1  gelu(Xg[e] @ w1[e] + b1[e]) -> g_hh (fp16)
// MODE 1: FFN2  (H[e] @ w2[e] + b2[e]) atomic-> g_eo (fp32)
// MODE 2: LM    g_eoh @ lm_w + lm_b -> out
// A: fp16 smem (80B rows, ldmatrix). B: fp16 smem [k][n] 256B rows, chunk XOR
// swizzle c^(k&7), fragments via ldmatrix.x4.trans. grid.x = M tiles (L2 reuse).

#define SAH 80                      // A smem row stride in BYTES
#define ABUF (128 * SAH)            // 10240
#define BBUF (KC * 256)             // 8192  (32 k-rows x 128 n fp16)
#define BSOFF (2 * ABUF)            // 20480
#define LISTOFF (BSOFF + 2 * BBUF)  // 36864
#define SMEMSZ (LISTOFF + 512)      // 37376

template <int MODE>
__global__ void __launch_bounds__(256) gemm_mma(
    const __half* __restrict__ Bg16base,
    const float* __restrict__ bias,
    float* __restrict__ Out,
    int Ktot, int ldb)
{
    int e = blockIdx.z;
    int cnt = (MODE == 2) ? TTOK : g_cnt[e];
    int m0 = blockIdx.x * 128;
    int n0 = blockIdx.y * 128;
    if (m0 >= cnt) return;

    extern __shared__ char smem[];
    int* s_list = (int*)(smem + LISTOFF);
    uint32_t sbase = smem_u32(smem);

    int tid = threadIdx.x;
    int lane = tid & 31;
    int wid = tid >> 5;
    int wm = wid >> 2;       // 0..1  (m)
    int wn = wid & 3;        // 0..3  (n)

    const __half* Bg;
    const float* be;
    if (MODE == 0)      { Bg = Bg16base + (size_t)e * HDIM * IDIM; be = bias + (size_t)e * IDIM; }
    else if (MODE == 1) { Bg = Bg16base + (size_t)e * IDIM * HDIM; be = bias + (size_t)e * HDIM; }
    else                { Bg = Bg16base; be = bias; }

    if (MODE != 2 && tid < 128) {
        int gm = m0 + tid;
        s_list[tid] = (gm < cnt) ? g_list[e][gm] : -1;
    }
    __syncthreads();

    // ---- A cp.async: row = tid>>1, two 16B chunks ----
    int arow_i = tid >> 1;
    int ac4 = (tid & 1) * 2;
    const __half* asrc;
    uint32_t apred;
    if (MODE == 0) {
        int tok = s_list[arow_i];
        asrc = (tok >= 0) ? g_xh + (size_t)tok * HDIM + ac4 * 8 : g_xh;
        apred = (tok >= 0) ? 16u : 0u;
    } else if (MODE == 1) {
        bool v = (m0 + arow_i) < cnt;
        asrc = v ? g_hh + ((size_t)e * TTOK + m0 + arow_i) * IDIM + ac4 * 8 : g_hh;
        apred = v ? 16u : 0u;
    } else {
        asrc = g_eoh + (size_t)(m0 + arow_i) * HDIM + ac4 * 8;
        apred = 16u;
    }
    uint32_t adst = sbase + (uint32_t)(arow_i * SAH + ac4 * 16);

    // ---- B cp.async: 512 chunks (32 k x 16 c), thread -> ids tid*2, tid*2+1 ----
    int bk[2], bc[2];
    uint32_t bdst[2];
#pragma unroll
    for (int i = 0; i < 2; i++) {
        int id = tid * 2 + i;
        bk[i] = id >> 4;
        bc[i] = id & 15;
        bdst[i] = sbase + BSOFF + (uint32_t)(bk[i] * 256 + ((bc[i] ^ (bk[i] & 7)) << 4));
    }

    float d[4][4][4];
#pragma unroll
    for (int i = 0; i < 4; i++)
#pragma unroll
        for (int j = 0; j < 4; j++)
#pragma unroll
            for (int r = 0; r < 4; r++) d[i][j][r] = 0.f;

    int nit = Ktot / KC;

    // prefetch tile 0
    CP16Z(adst, asrc, apred);
    CP16Z(adst + 16, asrc + 8, apred);
#pragma unroll
    for (int i = 0; i < 2; i++)
        CP16Z(bdst[i], Bg + (size_t)bk[i] * ldb + n0 + bc[i] * 8, 16u);
    CPCOMMIT();

    // A ldmatrix lane address
    int mat = lane >> 3;
    int rl8 = lane & 7;
    uint32_t a_lane_off =
        (uint32_t)((wm * 64 + (mat & 1) * 8 + rl8) * SAH + (mat >> 1) * 16);
    // B trans-ldmatrix lane offsets for jj=0,1 (each covers 2 j-groups)
    //   mat: 0=(klo,j0) 1=(khi,j0) 2=(klo,j1) 3=(khi,j1)
    uint32_t b_lane_off[2];
#pragma unroll
    for (int jj = 0; jj < 2; jj++) {
        int jgrp = jj * 2 + (mat >> 1);
        int nb = wn * 4 + jgrp;
        int kk = (mat & 1) * 8 + rl8;
        b_lane_off[jj] = (uint32_t)(kk * 256 + ((nb ^ rl8) << 4));
    }

    for (int it = 0; it < nit; ++it) {
        int buf = it & 1;
        if (it + 1 < nit) {
            int nbuf = (it + 1) & 1;
            int k0 = (it + 1) * KC;
            uint32_t ao = (uint32_t)(nbuf * ABUF);
            uint32_t bo = (uint32_t)(nbuf * BBUF);
            CP16Z(adst + ao, asrc + k0, apred);
            CP16Z(adst + ao + 16, asrc + k0 + 8, apred);
#pragma unroll
            for (int i = 0; i < 2; i++)
                CP16Z(bdst[i] + bo, Bg + (size_t)(k0 + bk[i]) * ldb + n0 + bc[i] * 8, 16u);
            CPCOMMIT();
            CPWAIT(1);
        } else {
            CPWAIT(0);
        }
        __syncthreads();

        uint32_t abase = sbase + (uint32_t)(buf * ABUF) + a_lane_off;
        uint32_t bbase = sbase + BSOFF + (uint32_t)(buf * BBUF);
#pragma unroll
        for (int ks = 0; ks < 2; ks++) {
            uint32_t a[4][4];
#pragma unroll
            for (int i = 0; i < 4; i++)
                LDMX4(a[i], abase + (uint32_t)(i * 16 * SAH + ks * 32));
            uint32_t b[4][2];
#pragma unroll
            for (int jj = 0; jj < 2; jj++)
                LDMX4T(b[jj * 2][0], b[jj * 2][1], b[jj * 2 + 1][0], b[jj * 2 + 1][1],
                       bbase + (uint32_t)(ks * 16 * 256) + b_lane_off[jj]);
#pragma unroll
            for (int i = 0; i < 4; i++)
#pragma unroll
                for (int j = 0; j < 4; j++) MMA_F16(d[i][j], a[i], b[j]);
        }
        __syncthreads();
    }

    // ---- epilogue ----
    int row_l0 = wm * 64 + (lane >> 2);
    int col_l0 = wn * 32 + (lane & 3) * 2;
    float2 bj[4];
#pragma unroll
    for (int j = 0; j < 4; j++) {
        bj[j].x = be[n0 + col_l0 + j * 8];
        bj[j].y = be[n0 + col_l0 + j * 8 + 1];
    }

#pragma unroll
    for (int i = 0; i < 4; i++) {
        int rl = row_l0 + i * 16;
#pragma unroll
        for (int half = 0; half < 2; half++) {
            int r = rl + half * 8;
            int m = m0 + r;
            if (MODE != 2 && m >= cnt) continue;
#pragma unroll
            for (int j = 0; j < 4; j++) {
                int cl = col_l0 + j * 8;
                float v0 = d[i][j][half * 2 + 0] + bj[j].x;
                float v1 = d[i][j][half * 2 + 1] + bj[j].y;
                if (MODE == 0) {
                    v0 = 0.5f * v0 * (1.0f + erff(v0 * 0.70710678118654752f));
                    v1 = 0.5f * v1 * (1.0f + erff(v1 * 0.70710678118654752f));
                    uint32_t* dst = (uint32_t*)(g_hh + ((size_t)e * TTOK + m) * IDIM + n0 + cl);
                    *dst = f2h2(v1, v0);
                } else if (MODE == 1) {
                    int tok = s_list[r];
                    float* dst = g_eo + (size_t)tok * HDIM + n0 + cl;
                    atomicAdd(dst + 0, v0);
                    atomicAdd(dst + 1, v1);
                } else {
                    float* dst = Out + (size_t)m * VDIM + n0 + cl;
                    *(float2*)dst = make_float2(v0, v1);
                }
            }
        }
    }
}

// ======================= launcher =======================
extern "C" void kernel_launch(void* const* d_in, const int* in_sizes, int n_in,
                              void* d_out, int out_size) {
    const int*   ids = (const int*)d_in[0];
    const float* emb = (const float*)d_in[1];
    const float* rw  = (const float*)d_in[2];
    const float* rb  = (const float*)d_in[3];
    const float* w1  = (const float*)d_in[4];
    const float* b1  = (const float*)d_in[5];
    const float* w2  = (const float*)d_in[6];
    const float* b2  = (const float*)d_in[7];
    const float* lw  = (const float*)d_in[8];
    const float* lb  = (const float*)d_in[9];

    float* out = (float*)d_out;
    const size_t LOG = (size_t)TTOK * VDIM;
    float* out_rw = nullptr;
    float* out_se = nullptr;
    if ((size_t)out_size >= LOG + (size_t)2 * TTOK * KTOP) {
        out_rw = out + LOG;
        out_se = out + LOG + (size_t)TTOK * KTOP;
    }

    __half* w1h; __half* w2h; __half* lwh;
    cudaGetSymbolAddress((void**)&w1h, g_w1h);
    cudaGetSymbolAddress((void**)&w2h, g_w2h);
    cudaGetSymbolAddress((void**)&lwh, g_lwh);

    // weight conversion (fp32 -> fp16), grid-stride
    cvt_w_kernel<<<8192, 256>>>(w1, w1h, (int)((size_t)ENUM * HDIM * IDIM / 4));
    cvt_w_kernel<<<8192, 256>>>(w2, w2h, (int)((size_t)ENUM * IDIM * HDIM / 4));
    cvt_w_kernel<<<8192, 256>>>(lw, lwh, (int)((size_t)HDIM * VDIM / 4));

    setup_kernel<<<TTOK, 128>>>(ids, emb, rw, rb, out_rw, out_se);
    build_lists_kernel<<<ENUM, 256>>>();
    zero_eo_kernel<<<(TTOK * HDIM / 4 + 255) / 256, 256>>>();
    gemm_mma<0><<<dim3(TTOK / 128, IDIM / 128, ENUM), 256, SMEMSZ>>>(w1h, b1, nullptr, HDIM, IDIM);
    gemm_mma<1><<<dim3(TTOK / 128, HDIM / 128, ENUM), 256, SMEMSZ>>>(w2h, b2, nullptr, IDIM, HDIM);
    cvt_eo_kernel<<<(TTOK * HDIM / 4 + 255) / 256, 256>>>();
    gemm_mma<2><<<dim3(TTOK / 128, VDIM / 128, 1), 256, SMEMSZ>>>(lwh, lb, out, HDIM, VDIM);
}

// round 15
// speedup vs baseline: 1.0011x; 1.0011x over previous
#include <cuda_runtime.h>
#include <cuda_fp16.h>
#include <math.h>
#include <stdint.h>

#define TTOK 2048
#define HDIM 1024
#define ENUM 8
#define IDIM 4096
#define VDIM 32000
#define KTOP 2
#define KC   64

// ---- static scratch (no allocation allowed) ----
__device__ __half g_xh[(size_t)TTOK * HDIM];              // fp16 activations
__device__ __half g_hh[(size_t)ENUM * TTOK * IDIM];       // fp16 expert hidden
__device__ float  g_eo[(size_t)TTOK * HDIM];              // fp32 atomic combine
__device__ __half g_eoh[(size_t)TTOK * HDIM];             // fp16 copy for LM head
__device__ __half g_w1h[(size_t)ENUM * HDIM * IDIM];      // fp16 w1
__device__ __half g_w2h[(size_t)ENUM * IDIM * HDIM];      // fp16 w2
__device__ __half g_lwh[(size_t)HDIM * VDIM];             // fp16 lm_w
__device__ int    g_sel[TTOK * KTOP];
__device__ int    g_list[ENUM][TTOK];
__device__ int    g_cnt[ENUM];

// ======================= helpers =======================
__device__ __forceinline__ uint32_t smem_u32(const void* p) {
    uint32_t a;
    asm("{ .reg .u64 t; cvta.to.shared.u64 t, %1; cvt.u32.u64 %0, t; }" : "=r"(a) : "l"(p));
    return a;
}
__device__ __forceinline__ uint32_t f2h2(float hi, float lo) {
    uint32_t r;
    asm("cvt.rn.f16x2.f32 %0, %1, %2;" : "=r"(r) : "f"(hi), "f"(lo));
    return r;
}
#define CP16Z(dst, src, sz) \
    asm volatile("cp.async.cg.shared.global [%0], [%1], 16, %2;" \
                 :: "r"(dst), "l"(src), "r"(sz))
#define CPCOMMIT() asm volatile("cp.async.commit_group;")
#define CPWAIT(n)  asm volatile("cp.async.wait_group %0;" :: "n"(n))

#define LDMX4(r, addr)                                                         \
    asm volatile("ldmatrix.sync.aligned.m8n8.x4.shared.b16 {%0,%1,%2,%3}, [%4];" \
        : "=r"((r)[0]), "=r"((r)[1]), "=r"((r)[2]), "=r"((r)[3]) : "r"(addr))

#define LDMX4T(r0, r1, r2, r3, addr)                                           \
    asm volatile("ldmatrix.sync.aligned.m8n8.x4.trans.shared.b16 {%0,%1,%2,%3}, [%4];" \
        : "=r"(r0), "=r"(r1), "=r"(r2), "=r"(r3) : "r"(addr))

#define MMA_F16(d, a, b)                                                       \
    asm volatile(                                                              \
        "mma.sync.aligned.m16n8k16.row.col.f32.f16.f16.f32 "                   \
        "{%0,%1,%2,%3},{%4,%5,%6,%7},{%8,%9},{%0,%1,%2,%3};"                   \
        : "+f"((d)[0]), "+f"((d)[1]), "+f"((d)[2]), "+f"((d)[3])               \
        : "r"((a)[0]), "r"((a)[1]), "r"((a)[2]), "r"((a)[3]),                  \
          "r"((b)[0]), "r"((b)[1]))

// ======================= small kernels =======================
__global__ void cvt_w_kernel(const float* __restrict__ src, __half* __restrict__ dst,
                             int n4) {
    int i = blockIdx.x * blockDim.x + threadIdx.x;
    int stride = gridDim.x * blockDim.x;
    for (; i < n4; i += stride) {
        float4 v = ((const float4*)src)[i];
        uint2 h;
        h.x = f2h2(v.y, v.x);
        h.y = f2h2(v.w, v.z);
        ((uint2*)dst)[i] = h;
    }
}

__global__ void setup_kernel(const int* __restrict__ ids,
                             const float* __restrict__ emb,
                             const float* __restrict__ rw,
                             const float* __restrict__ rb,
                             float* __restrict__ out_rw,
                             float* __restrict__ out_se) {
    int t = blockIdx.x;
    int tid = threadIdx.x;
    int row = ids[t];
    const float* src = emb + (size_t)row * HDIM;
    const float4* s4 = (const float4*)src;
    uint2* dh = (uint2*)(g_xh + (size_t)t * HDIM);
    for (int i = tid; i < HDIM / 4; i += blockDim.x) {
        float4 v = s4[i];
        uint2 h;
        h.x = f2h2(v.y, v.x);
        h.y = f2h2(v.w, v.z);
        dh[i] = h;
    }

    float acc[ENUM];
#pragma unroll
    for (int e = 0; e < ENUM; e++) acc[e] = 0.f;
    for (int k = tid; k < HDIM; k += blockDim.x) {
        float xv = src[k];
        const float* wr = rw + (size_t)k * ENUM;
#pragma unroll
        for (int e = 0; e < ENUM; e++) acc[e] = fmaf(xv, wr[e], acc[e]);
    }
    __shared__ float sred[ENUM][128];
#pragma unroll
    for (int e = 0; e < ENUM; e++) sred[e][tid] = acc[e];
    __syncthreads();
    for (int s = 64; s > 0; s >>= 1) {
        if (tid < s) {
#pragma unroll
            for (int e = 0; e < ENUM; e++) sred[e][tid] += sred[e][tid + s];
        }
        __syncthreads();
    }
    if (tid == 0) {
        float lg[ENUM];
#pragma unroll
        for (int e = 0; e < ENUM; e++) lg[e] = sred[e][0] + rb[e];
        int i0 = 0; float v0 = lg[0];
#pragma unroll
        for (int e = 1; e < ENUM; e++) if (lg[e] > v0) { v0 = lg[e]; i0 = e; }
        int i1 = -1; float v1 = -3.0e38f;
#pragma unroll
        for (int e = 0; e < ENUM; e++) if (e != i0 && lg[e] > v1) { v1 = lg[e]; i1 = e; }
        float ee = expf(v1 - v0);
        float denom = 1.0f + ee;
        g_sel[t * 2 + 0] = i0;
        g_sel[t * 2 + 1] = i1;
        if (out_rw) { out_rw[t * 2 + 0] = 1.0f / denom; out_rw[t * 2 + 1] = ee / denom; }
        if (out_se) { out_se[t * 2 + 0] = (float)i0; out_se[t * 2 + 1] = (float)i1; }
    }
}

__global__ void build_lists_kernel() {
    int e = blockIdx.x;
    int tid = threadIdx.x;
    int lane = tid & 31, wid = tid >> 5;
    __shared__ int wtot[8];
    __shared__ int s_base;
    if (tid == 0) s_base = 0;
    __syncthreads();
    for (int base = 0; base < TTOK; base += 256) {
        int t = base + tid;
        int f = (g_sel[t * 2] == e || g_sel[t * 2 + 1] == e) ? 1 : 0;
        unsigned bal = __ballot_sync(0xffffffffu, f);
        int lpfx = __popc(bal & ((1u << lane) - 1u));
        if (lane == 0) wtot[wid] = __popc(bal);
        __syncthreads();
        int woff = 0;
        for (int w = 0; w < wid; w++) woff += wtot[w];
        if (f) g_list[e][s_base + woff + lpfx] = t;
        int tot = 0;
        for (int w = 0; w < 8; w++) tot += wtot[w];
        __syncthreads();
        if (tid == 0) s_base += tot;
        __syncthreads();
    }
    if (tid == 0) g_cnt[e] = s_base;
}

__global__ void zero_eo_kernel() {
    size_t i = (size_t)blockIdx.x * blockDim.x + threadIdx.x;
    if (i < (size_t)TTOK * HDIM / 4) {
        ((float4*)g_eo)[i] = make_float4(0.f, 0.f, 0.f, 0.f);
    }
}

__global__ void cvt_eo_kernel() {
    size_t i = (size_t)blockIdx.x * blockDim.x + threadIdx.x;
    if (i < (size_t)TTOK * HDIM / 4) {
        float4 v = ((float4*)g_eo)[i];
        uint2 h;
        h.x = f2h2(v.y, v.x);
        h.y = f2h2(v.w, v.z);
        ((uint2*)g_eoh)[i] = h;
    }
}

// ======================= fp16 mma.sync GEMM, KC=64, XOR-swizzled A and B ===========
// MODE 0: FFN1  gelu(Xg[e] @ w1[e] + b1[e]) -> g_hh (fp16)
// MODE 1: FFN2  (H[e] @ w2[e] + b2[e]) atomic-> g_eo (fp32)
// MODE 2: LM    g_eoh @ lm_w + lm_b -> out
// A smem: 128 rows x 128B (KC=64 halves), chunk swizzle c^(r&7).
// B smem: 64 k-rows x 256B (128 n halves), chunk swizzle c^(k&7).
// Fragments: ldmatrix.x4 (A) / ldmatrix.x4.trans (B). grid.x = M tiles (L2 reuse).

#define ABUF 16384
#define BBUF 16384
#define BSOFF (2 * ABUF)            // 32768
#define LISTOFF (BSOFF + 2 * BBUF)  // 65536
#define SMEMSZ (LISTOFF + 512)      // 66048

template <int MODE>
__global__ void __launch_bounds__(256) gemm_mma(
    const __half* __restrict__ Bg16base,
    const float* __restrict__ bias,
    float* __restrict__ Out,
    int Ktot, int ldb)
{
    int e = blockIdx.z;
    int cnt = (MODE == 2) ? TTOK : g_cnt[e];
    int m0 = blockIdx.x * 128;
    int n0 = blockIdx.y * 128;
    if (m0 >= cnt) return;

    extern __shared__ char smem[];
    int* s_list = (int*)(smem + LISTOFF);
    uint32_t sbase = smem_u32(smem);

    int tid = threadIdx.x;
    int lane = tid & 31;
    int wid = tid >> 5;
    int wm = wid >> 2;       // 0..1  (m)
    int wn = wid & 3;        // 0..3  (n)

    const __half* Bg;
    const float* be;
    if (MODE == 0)      { Bg = Bg16base + (size_t)e * HDIM * IDIM; be = bias + (size_t)e * IDIM; }
    else if (MODE == 1) { Bg = Bg16base + (size_t)e * IDIM * HDIM; be = bias + (size_t)e * HDIM; }
    else                { Bg = Bg16base; be = bias; }

    if (MODE != 2 && tid < 128) {
        int gm = m0 + tid;
        s_list[tid] = (gm < cnt) ? g_list[e][gm] : -1;
    }
    __syncthreads();

    // ---- A cp.async: row = tid>>1, 4 chunks c=(tid&1)*4+j ----
    int arow_i = tid >> 1;
    int ac0 = (tid & 1) * 4;
    const __half* asrc;
    uint32_t apred;
    if (MODE == 0) {
        int tok = s_list[arow_i];
        asrc = (tok >= 0) ? g_xh + (size_t)tok * HDIM + ac0 * 8 : g_xh;
        apred = (tok >= 0) ? 16u : 0u;
    } else if (MODE == 1) {
        bool v = (m0 + arow_i) < cnt;
        asrc = v ? g_hh + ((size_t)e * TTOK + m0 + arow_i) * IDIM + ac0 * 8 : g_hh;
        apred = v ? 16u : 0u;
    } else {
        asrc = g_eoh + (size_t)(m0 + arow_i) * HDIM + ac0 * 8;
        apred = 16u;
    }
    uint32_t adst[4];
#pragma unroll
    for (int j = 0; j < 4; j++) {
        int c = ac0 + j;
        adst[j] = sbase + (uint32_t)(arow_i * 128 + ((c ^ (arow_i & 7)) << 4));
    }

    // ---- B cp.async: k = tid>>2 (0..63), 4 chunks c=(tid&3)*4+i ----
    int bk = tid >> 2;
    int bc0 = (tid & 3) * 4;
    uint32_t bdst[4];
#pragma unroll
    for (int i = 0; i < 4; i++) {
        int c = bc0 + i;
        bdst[i] = sbase + BSOFF + (uint32_t)(bk * 256 + ((c ^ (bk & 7)) << 4));
    }
    const __half* bsrc = Bg + (size_t)bk * ldb + n0 + bc0 * 8;

    float d[4][4][4];
#pragma unroll
    for (int i = 0; i < 4; i++)
#pragma unroll
        for (int j = 0; j < 4; j++)
#pragma unroll
            for (int r = 0; r < 4; r++) d[i][j][r] = 0.f;

    int nit = Ktot / KC;

    // prefetch tile 0
#pragma unroll
    for (int j = 0; j < 4; j++) CP16Z(adst[j], asrc + j * 8, apred);
#pragma unroll
    for (int i = 0; i < 4; i++) CP16Z(bdst[i], bsrc + i * 8, 16u);
    CPCOMMIT();

    // fragment lane addressing
    int mat = lane >> 3;         // 0..3
    int rl8 = lane & 7;
    int m2 = mat >> 1;           // k-half selector
    // A: row = wm*64 + (mat&1)*8 + rl8 (+ i*16); chunk = ks*2 + m2, XOR rl8
    uint32_t a_row_byte = (uint32_t)((wm * 64 + (mat & 1) * 8 + rl8) * 128);
    // B: koff = (mat&1)*8 + rl8; nb = wn*4 + jj*2 + m2, XOR rl8
    uint32_t b_koff_byte = (uint32_t)(((mat & 1) * 8 + rl8) * 256);
    uint32_t b_nb[2];
#pragma unroll
    for (int jj = 0; jj < 2; jj++)
        b_nb[jj] = (uint32_t)(((wn * 4 + jj * 2 + m2) ^ rl8) << 4);

    for (int it = 0; it < nit; ++it) {
        int buf = it & 1;
        if (it + 1 < nit) {
            int nbuf = (it + 1) & 1;
            int k0 = (it + 1) * KC;
            uint32_t ao = (uint32_t)(nbuf * ABUF);
            uint32_t bo = (uint32_t)(nbuf * BBUF);
#pragma unroll
            for (int j = 0; j < 4; j++) CP16Z(adst[j] + ao, asrc + k0 + j * 8, apred);
#pragma unroll
            for (int i = 0; i < 4; i++)
                CP16Z(bdst[i] + bo, bsrc + (size_t)k0 * ldb + i * 8, 16u);
            CPCOMMIT();
            CPWAIT(1);
        } else {
            CPWAIT(0);
        }
        __syncthreads();

        uint32_t abase = sbase + (uint32_t)(buf * ABUF) + a_row_byte;
        uint32_t bbase = sbase + BSOFF + (uint32_t)(buf * BBUF) + b_koff_byte;
#pragma unroll
        for (int ks = 0; ks < 4; ks++) {
            uint32_t a_sw = (uint32_t)(((ks * 2 + m2) ^ rl8) << 4);
            uint32_t a[4][4];
#pragma unroll
            for (int i = 0; i < 4; i++)
                LDMX4(a[i], abase + (uint32_t)(i * 2048) + a_sw);
            uint32_t b[4][2];
#pragma unroll
            for (int jj = 0; jj < 2; jj++)
                LDMX4T(b[jj * 2][0], b[jj * 2][1], b[jj * 2 + 1][0], b[jj * 2 + 1][1],
                       bbase + (uint32_t)(ks * 4096) + b_nb[jj]);
#pragma unroll
            for (int i = 0; i < 4; i++)
#pragma unroll
                for (int j = 0; j < 4; j++) MMA_F16(d[i][j], a[i], b[j]);
        }
        __syncthreads();
    }

    // ---- epilogue ----
    int row_l0 = wm * 64 + (lane >> 2);
    int col_l0 = wn * 32 + (lane & 3) * 2;
    float2 bj[4];
#pragma unroll
    for (int j = 0; j < 4; j++) {
        bj[j].x = be[n0 + col_l0 + j * 8];
        bj[j].y = be[n0 + col_l0 + j * 8 + 1];
    }

#pragma unroll
    for (int i = 0; i < 4; i++) {
        int rl = row_l0 + i * 16;
#pragma unroll
        for (int half = 0; half < 2; half++) {
            int r = rl + half * 8;
            int m = m0 + r;
            if (MODE != 2 && m >= cnt) continue;
#pragma unroll
            for (int j = 0; j < 4; j++) {
                int cl = col_l0 + j * 8;
                float v0 = d[i][j][half * 2 + 0] + bj[j].x;
                float v1 = d[i][j][half * 2 + 1] + bj[j].y;
                if (MODE == 0) {
                    v0 = 0.5f * v0 * (1.0f + erff(v0 * 0.70710678118654752f));
                    v1 = 0.5f * v1 * (1.0f + erff(v1 * 0.70710678118654752f));
                    uint32_t* dst = (uint32_t*)(g_hh + ((size_t)e * TTOK + m) * IDIM + n0 + cl);
                    *dst = f2h2(v1, v0);
                } else if (MODE == 1) {
                    int tok = s_list[r];
                    float* dst = g_eo + (size_t)tok * HDIM + n0 + cl;
                    atomicAdd(dst + 0, v0);
                    atomicAdd(dst + 1, v1);
                } else {
                    float* dst = Out + (size_t)m * VDIM + n0 + cl;
                    *(float2*)dst = make_float2(v0, v1);
                }
            }
        }
    }
}

// ======================= launcher =======================
extern "C" void kernel_launch(void* const* d_in, const int* in_sizes, int n_in,
                              void* d_out, int out_size) {
    const int*   ids = (const int*)d_in[0];
    const float* emb = (const float*)d_in[1];
    const float* rw  = (const float*)d_in[2];
    const float* rb  = (const float*)d_in[3];
    const float* w1  = (const float*)d_in[4];
    const float* b1  = (const float*)d_in[5];
    const float* w2  = (const float*)d_in[6];
    const float* b2  = (const float*)d_in[7];
    const float* lw  = (const float*)d_in[8];
    const float* lb  = (const float*)d_in[9];

    float* out = (float*)d_out;
    const size_t LOG = (size_t)TTOK * VDIM;
    float* out_rw = nullptr;
    float* out_se = nullptr;
    if ((size_t)out_size >= LOG + (size_t)2 * TTOK * KTOP) {
        out_rw = out + LOG;
        out_se = out + LOG + (size_t)TTOK * KTOP;
    }

    __half* w1h; __half* w2h; __half* lwh;
    cudaGetSymbolAddress((void**)&w1h, g_w1h);
    cudaGetSymbolAddress((void**)&w2h, g_w2h);
    cudaGetSymbolAddress((void**)&lwh, g_lwh);

    static bool attr_done = false;
    if (!attr_done) {
        cudaFuncSetAttribute(gemm_mma<0>, cudaFuncAttributeMaxDynamicSharedMemorySize, SMEMSZ);
        cudaFuncSetAttribute(gemm_mma<1>, cudaFuncAttributeMaxDynamicSharedMemorySize, SMEMSZ);
        cudaFuncSetAttribute(gemm_mma<2>, cudaFuncAttributeMaxDynamicSharedMemorySize, SMEMSZ);
        attr_done = true;
    }

    // weight conversion (fp32 -> fp16), grid-stride
    cvt_w_kernel<<<8192, 256>>>(w1, w1h, (int)((size_t)ENUM * HDIM * IDIM / 4));
    cvt_w_kernel<<<8192, 256>>>(w2, w2h, (int)((size_t)ENUM * IDIM * HDIM / 4));
    cvt_w_kernel<<<8192, 256>>>(lw, lwh, (int)((size_t)HDIM * VDIM / 4));

    setup_kernel<<<TTOK, 128>>>(ids, emb, rw, rb, out_rw, out_se);
    build_lists_kernel<<<ENUM, 256>>>();
    zero_eo_kernel<<<(TTOK * HDIM / 4 + 255) / 256, 256>>>();
    gemm_mma<0><<<dim3(TTOK / 128, IDIM / 128, ENUM), 256, SMEMSZ>>>(w1h, b1, nullptr, HDIM, IDIM);
    gemm_mma<1><<<dim3(TTOK / 128, HDIM / 128, ENUM), 256, SMEMSZ>>>(w2h, b2, nullptr, IDIM, HDIM);
    cvt_eo_kernel<<<(TTOK * HDIM / 4 + 255) / 256, 256>>>();
    gemm_mma<2><<<dim3(TTOK / 128, VDIM / 128, 1), 256, SMEMSZ>>>(lwh, lb, out, HDIM, VDIM);
}

// round 16
// speedup vs baseline: 1.0205x; 1.0195x over previous
#include <cuda_runtime.h>
#include <cuda_fp16.h>
#include <math.h>
#include <stdint.h>

#define TTOK 2048
#define HDIM 1024
#define ENUM 8
#define IDIM 4096
#define VDIM 32000
#define KTOP 2
#define KC   64

// ---- static scratch (no allocation allowed) ----
__device__ __half g_xh[(size_t)TTOK * HDIM];              // fp16 activations
__device__ __half g_hh[(size_t)ENUM * TTOK * IDIM];       // fp16 expert hidden
__device__ float  g_eo[(size_t)TTOK * HDIM];              // fp32 atomic combine
__device__ __half g_eoh[(size_t)TTOK * HDIM];             // fp16 copy for LM head
__device__ __half g_w1h[(size_t)ENUM * HDIM * IDIM];      // fp16 w1
__device__ __half g_w2h[(size_t)ENUM * IDIM * HDIM];      // fp16 w2
__device__ __half g_lwh[(size_t)HDIM * VDIM];             // fp16 lm_w
__device__ int    g_sel[TTOK * KTOP];
__device__ int    g_list[ENUM][TTOK];
__device__ int    g_cnt[ENUM];

// ======================= helpers =======================
__device__ __forceinline__ uint32_t smem_u32(const void* p) {
    uint32_t a;
    asm("{ .reg .u64 t; cvta.to.shared.u64 t, %1; cvt.u32.u64 %0, t; }" : "=r"(a) : "l"(p));
    return a;
}
__device__ __forceinline__ uint32_t f2h2(float hi, float lo) {
    uint32_t r;
    asm("cvt.rn.f16x2.f32 %0, %1, %2;" : "=r"(r) : "f"(hi), "f"(lo));
    return r;
}
#define CP16Z(dst, src, sz) \
    asm volatile("cp.async.cg.shared.global [%0], [%1], 16, %2;" \
                 :: "r"(dst), "l"(src), "r"(sz))
#define CPCOMMIT() asm volatile("cp.async.commit_group;")
#define CPWAIT(n)  asm volatile("cp.async.wait_group %0;" :: "n"(n))

#define LDMX4(r, addr)                                                         \
    asm volatile("ldmatrix.sync.aligned.m8n8.x4.shared.b16 {%0,%1,%2,%3}, [%4];" \
        : "=r"((r)[0]), "=r"((r)[1]), "=r"((r)[2]), "=r"((r)[3]) : "r"(addr))

#define LDMX4T(r0, r1, r2, r3, addr)                                           \
    asm volatile("ldmatrix.sync.aligned.m8n8.x4.trans.shared.b16 {%0,%1,%2,%3}, [%4];" \
        : "=r"(r0), "=r"(r1), "=r"(r2), "=r"(r3) : "r"(addr))

#define MMA_F16(d, a, b)                                                       \
    asm volatile(                                                              \
        "mma.sync.aligned.m16n8k16.row.col.f32.f16.f16.f32 "                   \
        "{%0,%1,%2,%3},{%4,%5,%6,%7},{%8,%9},{%0,%1,%2,%3};"                   \
        : "+f"((d)[0]), "+f"((d)[1]), "+f"((d)[2]), "+f"((d)[3])               \
        : "r"((a)[0]), "r"((a)[1]), "r"((a)[2]), "r"((a)[3]),                  \
          "r"((b)[0]), "r"((b)[1]))

// ======================= small kernels =======================
__global__ void cvt_w_kernel(const float* __restrict__ src, __half* __restrict__ dst,
                             int n4) {
    int i = blockIdx.x * blockDim.x + threadIdx.x;
    int stride = gridDim.x * blockDim.x;
    for (; i < n4; i += stride) {
        float4 v = ((const float4*)src)[i];
        uint2 h;
        h.x = f2h2(v.y, v.x);
        h.y = f2h2(v.w, v.z);
        ((uint2*)dst)[i] = h;
    }
}

__global__ void setup_kernel(const int* __restrict__ ids,
                             const float* __restrict__ emb,
                             const float* __restrict__ rw,
                             const float* __restrict__ rb,
                             float* __restrict__ out_rw,
                             float* __restrict__ out_se) {
    int t = blockIdx.x;
    int tid = threadIdx.x;
    int row = ids[t];
    const float* src = emb + (size_t)row * HDIM;
    const float4* s4 = (const float4*)src;
    uint2* dh = (uint2*)(g_xh + (size_t)t * HDIM);
    for (int i = tid; i < HDIM / 4; i += blockDim.x) {
        float4 v = s4[i];
        uint2 h;
        h.x = f2h2(v.y, v.x);
        h.y = f2h2(v.w, v.z);
        dh[i] = h;
    }

    float acc[ENUM];
#pragma unroll
    for (int e = 0; e < ENUM; e++) acc[e] = 0.f;
    for (int k = tid; k < HDIM; k += blockDim.x) {
        float xv = src[k];
        const float* wr = rw + (size_t)k * ENUM;
#pragma unroll
        for (int e = 0; e < ENUM; e++) acc[e] = fmaf(xv, wr[e], acc[e]);
    }
    __shared__ float sred[ENUM][128];
#pragma unroll
    for (int e = 0; e < ENUM; e++) sred[e][tid] = acc[e];
    __syncthreads();
    for (int s = 64; s > 0; s >>= 1) {
        if (tid < s) {
#pragma unroll
            for (int e = 0; e < ENUM; e++) sred[e][tid] += sred[e][tid + s];
        }
        __syncthreads();
    }
    if (tid == 0) {
        float lg[ENUM];
#pragma unroll
        for (int e = 0; e < ENUM; e++) lg[e] = sred[e][0] + rb[e];
        int i0 = 0; float v0 = lg[0];
#pragma unroll
        for (int e = 1; e < ENUM; e++) if (lg[e] > v0) { v0 = lg[e]; i0 = e; }
        int i1 = -1; float v1 = -3.0e38f;
#pragma unroll
        for (int e = 0; e < ENUM; e++) if (e != i0 && lg[e] > v1) { v1 = lg[e]; i1 = e; }
        float ee = expf(v1 - v0);
        float denom = 1.0f + ee;
        g_sel[t * 2 + 0] = i0;
        g_sel[t * 2 + 1] = i1;
        if (out_rw) { out_rw[t * 2 + 0] = 1.0f / denom; out_rw[t * 2 + 1] = ee / denom; }
        if (out_se) { out_se[t * 2 + 0] = (float)i0; out_se[t * 2 + 1] = (float)i1; }
    }
}

__global__ void build_lists_kernel() {
    int e = blockIdx.x;
    int tid = threadIdx.x;
    int lane = tid & 31, wid = tid >> 5;
    __shared__ int wtot[8];
    __shared__ int s_base;
    if (tid == 0) s_base = 0;
    __syncthreads();
    for (int base = 0; base < TTOK; base += 256) {
        int t = base + tid;
        int f = (g_sel[t * 2] == e || g_sel[t * 2 + 1] == e) ? 1 : 0;
        unsigned bal = __ballot_sync(0xffffffffu, f);
        int lpfx = __popc(bal & ((1u << lane) - 1u));
        if (lane == 0) wtot[wid] = __popc(bal);
        __syncthreads();
        int woff = 0;
        for (int w = 0; w < wid; w++) woff += wtot[w];
        if (f) g_list[e][s_base + woff + lpfx] = t;
        int tot = 0;
        for (int w = 0; w < 8; w++) tot += wtot[w];
        __syncthreads();
        if (tid == 0) s_base += tot;
        __syncthreads();
    }
    if (tid == 0) g_cnt[e] = s_base;
}

__global__ void zero_eo_kernel() {
    size_t i = (size_t)blockIdx.x * blockDim.x + threadIdx.x;
    if (i < (size_t)TTOK * HDIM / 4) {
        ((float4*)g_eo)[i] = make_float4(0.f, 0.f, 0.f, 0.f);
    }
}

__global__ void cvt_eo_kernel() {
    size_t i = (size_t)blockIdx.x * blockDim.x + threadIdx.x;
    if (i < (size_t)TTOK * HDIM / 4) {
        float4 v = ((float4*)g_eo)[i];
        uint2 h;
        h.x = f2h2(v.y, v.x);
        h.y = f2h2(v.w, v.z);
        ((uint2*)g_eoh)[i] = h;
    }
}

// ======================= fp16 mma.sync GEMM, KC=64, XOR-swizzled A and B ===========
// MODE 0: FFN1  gelu(Xg[e] @ w1[e] + b1[e]) -> g_hh (fp16)
// MODE 1: FFN2  (H[e] @ w2[e] + b2[e]) atomic-> g_eo (fp32)
// MODE 2: LM    g_eoh @ lm_w + lm_b -> out

#define ABUF 16384
#define BBUF 16384
#define BSOFF (2 * ABUF)            // 32768
#define LISTOFF (BSOFF + 2 * BBUF)  // 65536
#define SMEMSZ (LISTOFF + 512)      // 66048

template <int MODE>
__global__ void __launch_bounds__(256) gemm_mma(
    const __half* __restrict__ Bg16base,
    const float* __restrict__ bias,
    float* __restrict__ Out,
    int Ktot, int ldb)
{
    int e = blockIdx.z;
    int cnt = (MODE == 2) ? TTOK : g_cnt[e];
    int m0 = blockIdx.x * 128;
    int n0 = blockIdx.y * 128;
    if (m0 >= cnt) return;

    extern __shared__ char smem[];
    int* s_list = (int*)(smem + LISTOFF);
    uint32_t sbase = smem_u32(smem);

    int tid = threadIdx.x;
    int lane = tid & 31;
    int wid = tid >> 5;
    int wm = wid >> 2;       // 0..1  (m)
    int wn = wid & 3;        // 0..3  (n)

    const __half* Bg;
    const float* be;
    if (MODE == 0)      { Bg = Bg16base + (size_t)e * HDIM * IDIM; be = bias + (size_t)e * IDIM; }
    else if (MODE == 1) { Bg = Bg16base + (size_t)e * IDIM * HDIM; be = bias + (size_t)e * HDIM; }
    else                { Bg = Bg16base; be = bias; }

    if (MODE != 2 && tid < 128) {
        int gm = m0 + tid;
        s_list[tid] = (gm < cnt) ? g_list[e][gm] : -1;
    }
    __syncthreads();

    // ---- A cp.async: row = tid>>1, 4 chunks c=(tid&1)*4+j ----
    int arow_i = tid >> 1;
    int ac0 = (tid & 1) * 4;
    const __half* asrc;
    uint32_t apred;
    if (MODE == 0) {
        int tok = s_list[arow_i];
        asrc = (tok >= 0) ? g_xh + (size_t)tok * HDIM + ac0 * 8 : g_xh;
        apred = (tok >= 0) ? 16u : 0u;
    } else if (MODE == 1) {
        bool v = (m0 + arow_i) < cnt;
        asrc = v ? g_hh + ((size_t)e * TTOK + m0 + arow_i) * IDIM + ac0 * 8 : g_hh;
        apred = v ? 16u : 0u;
    } else {
        asrc = g_eoh + (size_t)(m0 + arow_i) * HDIM + ac0 * 8;
        apred = 16u;
    }
    uint32_t adst[4];
#pragma unroll
    for (int j = 0; j < 4; j++) {
        int c = ac0 + j;
        adst[j] = sbase + (uint32_t)(arow_i * 128 + ((c ^ (arow_i & 7)) << 4));
    }

    // ---- B cp.async: k = tid>>2 (0..63), 4 chunks c=(tid&3)*4+i ----
    int bk = tid >> 2;
    int bc0 = (tid & 3) * 4;
    uint32_t bdst[4];
#pragma unroll
    for (int i = 0; i < 4; i++) {
        int c = bc0 + i;
        bdst[i] = sbase + BSOFF + (uint32_t)(bk * 256 + ((c ^ (bk & 7)) << 4));
    }
    const __half* bsrc = Bg + (size_t)bk * ldb + n0 + bc0 * 8;

    float d[4][4][4];
#pragma unroll
    for (int i = 0; i < 4; i++)
#pragma unroll
        for (int j = 0; j < 4; j++)
#pragma unroll
            for (int r = 0; r < 4; r++) d[i][j][r] = 0.f;

    int nit = Ktot / KC;

    // prefetch tile 0
#pragma unroll
    for (int j = 0; j < 4; j++) CP16Z(adst[j], asrc + j * 8, apred);
#pragma unroll
    for (int i = 0; i < 4; i++) CP16Z(bdst[i], bsrc + i * 8, 16u);
    CPCOMMIT();

    // fragment lane addressing
    int mat = lane >> 3;         // 0..3
    int rl8 = lane & 7;
    int m2 = mat >> 1;           // k-half selector
    uint32_t a_row_byte = (uint32_t)((wm * 64 + (mat & 1) * 8 + rl8) * 128);
    uint32_t b_koff_byte = (uint32_t)(((mat & 1) * 8 + rl8) * 256);
    uint32_t b_nb[2];
#pragma unroll
    for (int jj = 0; jj < 2; jj++)
        b_nb[jj] = (uint32_t)(((wn * 4 + jj * 2 + m2) ^ rl8) << 4);

    for (int it = 0; it < nit; ++it) {
        int buf = it & 1;
        if (it + 1 < nit) {
            int nbuf = (it + 1) & 1;
            int k0 = (it + 1) * KC;
            uint32_t ao = (uint32_t)(nbuf * ABUF);
            uint32_t bo = (uint32_t)(nbuf * BBUF);
#pragma unroll
            for (int j = 0; j < 4; j++) CP16Z(adst[j] + ao, asrc + k0 + j * 8, apred);
#pragma unroll
            for (int i = 0; i < 4; i++)
                CP16Z(bdst[i] + bo, bsrc + (size_t)k0 * ldb + i * 8, 16u);
            CPCOMMIT();
            CPWAIT(1);
        } else {
            CPWAIT(0);
        }
        __syncthreads();

        uint32_t abase = sbase + (uint32_t)(buf * ABUF) + a_row_byte;
        uint32_t bbase = sbase + BSOFF + (uint32_t)(buf * BBUF) + b_koff_byte;
#pragma unroll
        for (int ks = 0; ks < 4; ks++) {
            uint32_t a_sw = (uint32_t)(((ks * 2 + m2) ^ rl8) << 4);
            uint32_t a[4][4];
#pragma unroll
            for (int i = 0; i < 4; i++)
                LDMX4(a[i], abase + (uint32_t)(i * 2048) + a_sw);
            uint32_t b[4][2];
#pragma unroll
            for (int jj = 0; jj < 2; jj++)
                LDMX4T(b[jj * 2][0], b[jj * 2][1], b[jj * 2 + 1][0], b[jj * 2 + 1][1],
                       bbase + (uint32_t)(ks * 4096) + b_nb[jj]);
#pragma unroll
            for (int i = 0; i < 4; i++)
#pragma unroll
                for (int j = 0; j < 4; j++) MMA_F16(d[i][j], a[i], b[j]);
        }
        __syncthreads();
    }

    // ---- epilogue ----
    int row_l0 = wm * 64 + (lane >> 2);
    int col_l0 = wn * 32 + (lane & 3) * 2;
    float2 bj[4];
#pragma unroll
    for (int j = 0; j < 4; j++) {
        bj[j].x = be[n0 + col_l0 + j * 8];
        bj[j].y = be[n0 + col_l0 + j * 8 + 1];
    }

#pragma unroll
    for (int i = 0; i < 4; i++) {
        int rl = row_l0 + i * 16;
#pragma unroll
        for (int half = 0; half < 2; half++) {
            int r = rl + half * 8;
            int m = m0 + r;
            if (MODE != 2 && m >= cnt) continue;
#pragma unroll
            for (int j = 0; j < 4; j++) {
                int cl = col_l0 + j * 8;
                float v0 = d[i][j][half * 2 + 0] + bj[j].x;
                float v1 = d[i][j][half * 2 + 1] + bj[j].y;
                if (MODE == 0) {
                    v0 = 0.5f * v0 * (1.0f + erff(v0 * 0.70710678118654752f));
                    v1 = 0.5f * v1 * (1.0f + erff(v1 * 0.70710678118654752f));
                    uint32_t* dst = (uint32_t*)(g_hh + ((size_t)e * TTOK + m) * IDIM + n0 + cl);
                    *dst = f2h2(v1, v0);
                } else if (MODE == 1) {
                    int tok = s_list[r];
                    float* dst = g_eo + (size_t)tok * HDIM + n0 + cl;
                    atomicAdd(dst + 0, v0);
                    atomicAdd(dst + 1, v1);
                } else {
                    float* dst = Out + (size_t)m * VDIM + n0 + cl;
                    *(float2*)dst = make_float2(v0, v1);
                }
            }
        }
    }
}

// ======================= launcher (fork/join streams for conversion overlap) ==========
extern "C" void kernel_launch(void* const* d_in, const int* in_sizes, int n_in,
                              void* d_out, int out_size) {
    const int*   ids = (const int*)d_in[0];
    const float* emb = (const float*)d_in[1];
    const float* rw  = (const float*)d_in[2];
    const float* rb  = (const float*)d_in[3];
    const float* w1  = (const float*)d_in[4];
    const float* b1  = (const float*)d_in[5];
    const float* w2  = (const float*)d_in[6];
    const float* b2  = (const float*)d_in[7];
    const float* lw  = (const float*)d_in[8];
    const float* lb  = (const float*)d_in[9];

    float* out = (float*)d_out;
    const size_t LOG = (size_t)TTOK * VDIM;
    float* out_rw = nullptr;
    float* out_se = nullptr;
    if ((size_t)out_size >= LOG + (size_t)2 * TTOK * KTOP) {
        out_rw = out + LOG;
        out_se = out + LOG + (size_t)TTOK * KTOP;
    }

    __half* w1h; __half* w2h; __half* lwh;
    cudaGetSymbolAddress((void**)&w1h, g_w1h);
    cudaGetSymbolAddress((void**)&w2h, g_w2h);
    cudaGetSymbolAddress((void**)&lwh, g_lwh);

    static bool init_done = false;
    static cudaStream_t s1, s2, s3;
    static cudaEvent_t evRoot, evW1, ev1, ev2, ev3;
    if (!init_done) {
        cudaFuncSetAttribute(gemm_mma<0>, cudaFuncAttributeMaxDynamicSharedMemorySize, SMEMSZ);
        cudaFuncSetAttribute(gemm_mma<1>, cudaFuncAttributeMaxDynamicSharedMemorySize, SMEMSZ);
        cudaFuncSetAttribute(gemm_mma<2>, cudaFuncAttributeMaxDynamicSharedMemorySize, SMEMSZ);
        cudaStreamCreateWithFlags(&s1, cudaStreamNonBlocking);
        cudaStreamCreateWithFlags(&s2, cudaStreamNonBlocking);
        cudaStreamCreateWithFlags(&s3, cudaStreamNonBlocking);
        cudaEventCreateWithFlags(&evRoot, cudaEventDisableTiming);
        cudaEventCreateWithFlags(&evW1, cudaEventDisableTiming);
        cudaEventCreateWithFlags(&ev1, cudaEventDisableTiming);
        cudaEventCreateWithFlags(&ev2, cudaEventDisableTiming);
        cudaEventCreateWithFlags(&ev3, cudaEventDisableTiming);
        init_done = true;
    }

    // fork root
    cudaEventRecord(evRoot, 0);
    cudaStreamWaitEvent(s1, evRoot, 0);
    cudaStreamWaitEvent(s2, evRoot, 0);
    cudaStreamWaitEvent(s3, evRoot, 0);

    // s1: token-side setup (overlaps cvt_w1)
    setup_kernel<<<TTOK, 128, 0, s1>>>(ids, emb, rw, rb, out_rw, out_se);
    build_lists_kernel<<<ENUM, 256, 0, s1>>>();
    zero_eo_kernel<<<(TTOK * HDIM / 4 + 255) / 256, 256, 0, s1>>>();
    cudaEventRecord(ev1, s1);

    // stream0: w1 conversion (gates ffn1)
    cvt_w_kernel<<<8192, 256>>>(w1, w1h, (int)((size_t)ENUM * HDIM * IDIM / 4));
    cudaEventRecord(evW1, 0);

    // s2/s3: w2 + lm_w conversions overlap ffn1/ffn2 compute
    cudaStreamWaitEvent(s2, evW1, 0);
    cvt_w_kernel<<<8192, 256, 0, s2>>>(w2, w2h, (int)((size_t)ENUM * IDIM * HDIM / 4));
    cudaEventRecord(ev2, s2);
    cudaStreamWaitEvent(s3, evW1, 0);
    cvt_w_kernel<<<8192, 256, 0, s3>>>(lw, lwh, (int)((size_t)HDIM * VDIM / 4));
    cudaEventRecord(ev3, s3);

    // stream0: GEMM chain
    cudaStreamWaitEvent(0, ev1, 0);
    gemm_mma<0><<<dim3(TTOK / 128, IDIM / 128, ENUM), 256, SMEMSZ>>>(w1h, b1, nullptr, HDIM, IDIM);
    cudaStreamWaitEvent(0, ev2, 0);
    gemm_mma<1><<<dim3(TTOK / 128, HDIM / 128, ENUM), 256, SMEMSZ>>>(w2h, b2, nullptr, IDIM, HDIM);
    cvt_eo_kernel<<<(TTOK * HDIM / 4 + 255) / 256, 256>>>();
    cudaStreamWaitEvent(0, ev3, 0);
    gemm_mma<2><<<dim3(TTOK / 128, VDIM / 128, 1), 256, SMEMSZ>>>(lwh, lb, out, HDIM, VDIM);
}